// round 11
// baseline (speedup 1.0000x reference)
#include <cuda_runtime.h>
#include <cuda_fp16.h>
#include <math.h>
#include <stdint.h>

#define BB 2
#define NN 2048
#define CC 1024
#define HH 16
#define DD 64
#define FF 4096
#define TT (BB*NN)          // 4096 tokens

// ---------------- scratch (device globals) ----------------
__device__ __half g_xn  [(size_t)TT*CC];
__device__ __half g_qkv [(size_t)TT*3*CC];
__device__ __half g_y   [(size_t)TT*CC];
__device__ float  g_x1  [(size_t)TT*CC];
__device__ __half g_xn2 [(size_t)TT*CC];
__device__ __half g_h   [(size_t)TT*FF];
__device__ __half g_wqkv[(size_t)CC*3*CC];
__device__ __half g_wp  [(size_t)CC*CC];
__device__ __half g_w1  [(size_t)CC*FF];
__device__ __half g_w2  [(size_t)FF*CC];

// ---------------- helpers ----------------
__device__ __forceinline__ uint32_t smem_u32(const void* p) {
    return (uint32_t)__cvta_generic_to_shared(p);
}

__device__ __forceinline__ void mma_f16(float4& d,
    uint32_t a0, uint32_t a1, uint32_t a2, uint32_t a3, uint32_t b0, uint32_t b1)
{
    asm volatile(
        "mma.sync.aligned.m16n8k16.row.col.f32.f16.f16.f32 "
        "{%0,%1,%2,%3}, {%4,%5,%6,%7}, {%8,%9}, {%0,%1,%2,%3};\n"
        : "+f"(d.x), "+f"(d.y), "+f"(d.z), "+f"(d.w)
        : "r"(a0), "r"(a1), "r"(a2), "r"(a3), "r"(b0), "r"(b1));
}

__device__ __forceinline__ void ldsm_x4(uint32_t& r0, uint32_t& r1, uint32_t& r2, uint32_t& r3,
                                        uint32_t addr) {
    asm volatile("ldmatrix.sync.aligned.m8n8.x4.shared.b16 {%0,%1,%2,%3}, [%4];"
        : "=r"(r0), "=r"(r1), "=r"(r2), "=r"(r3) : "r"(addr));
}
__device__ __forceinline__ void ldsm_x4_t(uint32_t& r0, uint32_t& r1, uint32_t& r2, uint32_t& r3,
                                          uint32_t addr) {
    asm volatile("ldmatrix.sync.aligned.m8n8.x4.trans.shared.b16 {%0,%1,%2,%3}, [%4];"
        : "=r"(r0), "=r"(r1), "=r"(r2), "=r"(r3) : "r"(addr));
}
__device__ __forceinline__ void ldsm_x2_t(uint32_t& r0, uint32_t& r1, uint32_t addr) {
    asm volatile("ldmatrix.sync.aligned.m8n8.x2.trans.shared.b16 {%0,%1}, [%2];"
        : "=r"(r0), "=r"(r1) : "r"(addr));
}

__device__ __forceinline__ void cp16(void* smem_dst, const void* gsrc) {
    uint32_t d = smem_u32(smem_dst);
    asm volatile("cp.async.cg.shared.global [%0], [%1], 16;\n" :: "r"(d), "l"(gsrc));
}
__device__ __forceinline__ void cp_commit() { asm volatile("cp.async.commit_group;\n"); }
__device__ __forceinline__ void cp_wait0() { asm volatile("cp.async.wait_group 0;\n"); }
__device__ __forceinline__ void cp_wait1() { asm volatile("cp.async.wait_group 1;\n"); }
__device__ __forceinline__ void cp_wait2() { asm volatile("cp.async.wait_group 2;\n"); }

__device__ __forceinline__ uint32_t pkh2(float x, float y) {
    __half2 h = __floats2half2_rn(x, y);
    return *(uint32_t*)&h;
}
__device__ __forceinline__ uint32_t ex2h2(uint32_t a) {
    uint32_t d;
    asm("ex2.approx.f16x2 %0, %1;" : "=r"(d) : "r"(a));
    return d;
}

#define L2E 1.4426950408889634f

__device__ __forceinline__ float blockReduceSum256(float v) {
    __shared__ float sm[8];
    #pragma unroll
    for (int o = 16; o > 0; o >>= 1) v += __shfl_xor_sync(0xffffffffu, v, o);
    __syncthreads();
    if ((threadIdx.x & 31) == 0) sm[threadIdx.x >> 5] = v;
    __syncthreads();
    float t = 0.f;
    #pragma unroll
    for (int i = 0; i < 8; i++) t += sm[i];
    return t;
}

// ---------------- fused weight conversion: all 6 weights in one launch --------------
__global__ __launch_bounds__(256) void conv_all_kernel(
    const float* __restrict__ Wq, const float* __restrict__ Wk,
    const float* __restrict__ Wv, const float* __restrict__ Wp,
    const float* __restrict__ W1, const float* __restrict__ W2,
    __half* __restrict__ wqkv, __half* __restrict__ wp,
    __half* __restrict__ w1, __half* __restrict__ w2)
{
    const int blk = blockIdx.x;
    const float* in;
    __half* out;
    int cols, ldo, colofs, i0;
    float scale = 1.0f;
    if (blk < 4096) {
        cols = CC;
        if (blk < 1024)      { in = Wq; out = wqkv; ldo = 3 * CC; colofs = 0;      i0 = 0;    scale = 0.125f; }
        else if (blk < 2048) { in = Wk; out = wqkv; ldo = 3 * CC; colofs = CC;     i0 = 1024; }
        else if (blk < 3072) { in = Wv; out = wqkv; ldo = 3 * CC; colofs = 2 * CC; i0 = 2048; }
        else                 { in = Wp; out = wp;   ldo = CC;     colofs = 0;      i0 = 3072; }
    } else if (blk < 8192)   { in = W1; out = w1; cols = FF; ldo = FF; colofs = 0; i0 = 4096; }
    else                     { in = W2; out = w2; cols = CC; ldo = CC; colofs = 0; i0 = 8192; }

    int i = (blk - i0) * 256 + threadIdx.x;
    float4 v = ((const float4*)in)[i];
    int c4 = cols >> 2;
    int row = i / c4;
    int col = (i - row * c4) * 4;
    __half2* o = (__half2*)(out + (size_t)row * ldo + colofs + col);
    o[0] = __floats2half2_rn(v.x * scale, v.y * scale);
    o[1] = __floats2half2_rn(v.z * scale, v.w * scale);
}

// ---------------- layernorm: fp32 in -> fp16 out ----------------
__global__ __launch_bounds__(256) void layernorm_kernel(
    const float* __restrict__ x, const float* __restrict__ gamma,
    const float* __restrict__ beta, __half* __restrict__ out)
{
    const size_t row = (size_t)blockIdx.x * CC;
    const int c = threadIdx.x * 4;
    float4 v = *(const float4*)(x + row + c);

    float s = v.x + v.y + v.z + v.w;
    s = blockReduceSum256(s);
    float mu = s * (1.0f / CC);

    float dx = v.x - mu, dy = v.y - mu, dz = v.z - mu, dw = v.w - mu;
    float ss = dx*dx + dy*dy + dz*dz + dw*dw;
    ss = blockReduceSum256(ss);
    float rstd = rsqrtf(ss * (1.0f / CC) + 1e-6f);

    float4 g = *(const float4*)(gamma + c);
    float4 b = *(const float4*)(beta + c);
    __half2* o = (__half2*)(out + row + c);
    o[0] = __floats2half2_rn(dx * rstd * g.x + b.x, dy * rstd * g.y + b.y);
    o[1] = __floats2half2_rn(dz * rstd * g.z + b.z, dw * rstd * g.w + b.w);
}

// ---------------- fp16 GEMM 256x128x64, 512 thr, 3-stage cp.async ring ----------
// A [M][K] fp16 row-major, B [K][N] fp16 row-major
// smem: As [3*256][72], Bs [3*64][136]  -> 162816 B dynamic
#define GEMM_SMEM (3*256*72*2 + 3*64*136*2)

__global__ __launch_bounds__(512, 1) void h_gemm_kernel(
    const __half* __restrict__ A, const __half* __restrict__ Bm,
    const float* __restrict__ bias, const float* __restrict__ res,
    float* __restrict__ Cf, __half* __restrict__ Ch,
    int N, int K, int do_gelu)
{
    extern __shared__ char gsm[];
    __half (*As)[72]  = (__half(*)[72])gsm;                       // [3*256][72]
    __half (*Bs)[136] = (__half(*)[136])(gsm + 3 * 256 * 72 * 2); // [3*64][136]

    const int tid = threadIdx.x;
    const int lane = tid & 31;
    const int wid = tid >> 5;            // 0..15
    const int bx = blockIdx.x, by = blockIdx.y;
    const int m0w = (wid >> 2) * 64;     // 0,64,128,192
    const int n0w = (wid & 3) * 32;      // 0,32,64,96
    const int idx = lane & 7;
    const int sel = (lane >> 3) & 3;

    float4 acc[4][4];
    #pragma unroll
    for (int i = 0; i < 4; i++)
        #pragma unroll
        for (int j = 0; j < 4; j++) acc[i][j] = make_float4(0.f, 0.f, 0.f, 0.f);

    auto loadChunk = [&](int k0, int st) {
        #pragma unroll
        for (int i = 0; i < 4; i++) {
            int c = tid + i * 512;           // 2048 chunks for A (256x64)
            int r = c >> 3, c8 = (c & 7) * 8;
            cp16(&As[st * 256 + r][c8], A + (size_t)(by * 256 + r) * K + k0 + c8);
        }
        #pragma unroll
        for (int i = 0; i < 2; i++) {
            int c = tid + i * 512;           // 1024 chunks for B (64x128)
            int r = c >> 4, c8 = (c & 15) * 8;
            cp16(&Bs[st * 64 + r][c8], Bm + (size_t)(k0 + r) * N + bx * 128 + c8);
        }
        cp_commit();
    };

    const int KT = K >> 6;                  // >= 16 always
    loadChunk(0, 0);
    loadChunk(64, 1);
    for (int kt = 0; kt < KT; kt++) {
        if (kt + 1 < KT) cp_wait1(); else cp_wait0();
        __syncthreads();
        if (kt + 2 < KT) loadChunk((kt + 2) << 6, (kt + 2) % 3);

        const int st = kt % 3;
        #pragma unroll
        for (int kk = 0; kk < 64; kk += 16) {
            uint32_t af[4][4];
            #pragma unroll
            for (int im = 0; im < 4; im++)
                ldsm_x4(af[im][0], af[im][1], af[im][2], af[im][3],
                        smem_u32(&As[st * 256 + m0w + im * 16 + (lane & 15)][kk + ((lane >> 4) << 3)]));
            uint32_t bf[4][2];
            #pragma unroll
            for (int inp = 0; inp < 4; inp += 2)
                ldsm_x4_t(bf[inp][0], bf[inp][1], bf[inp + 1][0], bf[inp + 1][1],
                          smem_u32(&Bs[st * 64 + kk + (sel & 1) * 8 + idx][n0w + inp * 8 + (sel >> 1) * 8]));
            #pragma unroll
            for (int im = 0; im < 4; im++)
                #pragma unroll
                for (int in = 0; in < 4; in++)
                    mma_f16(acc[im][in], af[im][0], af[im][1], af[im][2], af[im][3],
                            bf[in][0], bf[in][1]);
        }
    }

    // epilogue
    #pragma unroll
    for (int im = 0; im < 4; im++) {
        #pragma unroll
        for (int in = 0; in < 4; in++) {
            int row = by * 256 + m0w + im * 16 + (lane >> 2);
            int col = bx * 128 + n0w + in * 8 + (lane & 3) * 2;
            #pragma unroll
            for (int half = 0; half < 2; half++) {
                int r = row + half * 8;
                float v0 = half ? acc[im][in].z : acc[im][in].x;
                float v1 = half ? acc[im][in].w : acc[im][in].y;
                if (bias) { v0 += bias[col]; v1 += bias[col + 1]; }
                if (do_gelu) {
                    v0 = 0.5f * v0 * (1.0f + erff(v0 * 0.70710678118654752f));
                    v1 = 0.5f * v1 * (1.0f + erff(v1 * 0.70710678118654752f));
                }
                if (res) {
                    v0 += res[(size_t)r * N + col];
                    v1 += res[(size_t)r * N + col + 1];
                }
                if (Ch) {
                    *(__half2*)(Ch + (size_t)r * N + col) = __floats2half2_rn(v0, v1);
                } else {
                    *(float2*)(Cf + (size_t)r * N + col) = make_float2(v0, v1);
                }
            }
        }
    }
}

// ---------------- fused flash attention: 64-key KV tiles, 3-stage ring, 2 CTA/SM ----
// grid (NN/128, B*H), 256 thr. Q tile 128 rows; KV tiles 64 rows, 3 stages.
// V smem col 64 = 1.0 (ones column) -> row sum l accumulates in extra MMA accum.
// smem: Q 128x72 + 3x64x72 (K) + 3x64x72 (V) = 73728 B
#define FLASH_SMEM_B ((128*72 + 3*64*72 + 3*64*72) * 2)

__global__ __launch_bounds__(256, 2) void flash_kernel(
    const __half* __restrict__ qkv, __half* __restrict__ y)
{
    extern __shared__ __half fsm[];
    __half (*Qs)[72] = (__half(*)[72])fsm;                            // 128x72
    __half (*Ks)[72] = (__half(*)[72])(fsm + 128 * 72);               // 3 x 64x72
    __half (*Vs)[72] = (__half(*)[72])(fsm + 128 * 72 + 3 * 64 * 72); // 3 x 64x72

    const int bh = blockIdx.y;
    const int b = bh >> 4, h = bh & 15;
    const int n0 = blockIdx.x * 128;
    const int tid = threadIdx.x;
    const int lane = tid & 31;
    const int wid = tid >> 5;
    const int idx = lane & 7;
    const int sel = (lane >> 3) & 3;

    const size_t tok0 = (size_t)b * NN;
    const __half* qb = qkv + h * DD;
    const __half* kb = qkv + CC + h * DD;
    const __half* vb = qkv + 2 * CC + h * DD;

    // Q tile: group 0
    #pragma unroll
    for (int i = 0; i < 4; i++) {
        int c = tid + i * 256;
        int r = c >> 3, c8 = (c & 7) * 8;
        cp16(&Qs[r][c8], qb + (tok0 + n0 + r) * (3 * CC) + c8);
    }
    cp_commit();

    auto loadKV = [&](int m0, int st) {
        #pragma unroll
        for (int i = 0; i < 2; i++) {
            int c = tid + i * 256;          // 512 chunks, 64 rows
            int r = c >> 3, c8 = (c & 7) * 8;
            cp16(&Ks[st * 64 + r][c8], kb + (tok0 + m0 + r) * (3 * CC) + c8);
        }
        #pragma unroll
        for (int i = 0; i < 2; i++) {
            int c = tid + i * 256;
            int r = c >> 3, c8 = (c & 7) * 8;
            cp16(&Vs[st * 64 + r][c8], vb + (tok0 + m0 + r) * (3 * CC) + c8);
        }
        cp_commit();
    };

    loadKV(0, 0);    // group 1
    loadKV(64, 1);   // group 2

    // ones column at V col 64, zeros 65-71 (all 3 stages = 192 rows; cols never overwritten)
    if (tid < 192) {
        __half* p = &Vs[tid][64];
        p[0] = __float2half(1.0f);
        #pragma unroll
        for (int j = 1; j < 8; j++) p[j] = __float2half(0.0f);
    }

    // Q ready after wait<=2 (groups 1,2 may still be in flight)
    cp_wait2();
    __syncthreads();
    uint32_t aq[4][4];
    #pragma unroll
    for (int kd = 0; kd < 4; kd++)
        ldsm_x4(aq[kd][0], aq[kd][1], aq[kd][2], aq[kd][3],
                smem_u32(&Qs[wid * 16 + (lane & 15)][kd * 16 + ((lane >> 4) << 3)]));

    float4 acc_o[8];
    float4 acc_l = make_float4(0.f, 0.f, 0.f, 0.f);
    #pragma unroll
    for (int i = 0; i < 8; i++) acc_o[i] = make_float4(0.f, 0.f, 0.f, 0.f);
    float mrow[2] = {-1e30f, -1e30f};

    const int NTILE = NN / 64;        // 32 KV tiles of 64 keys
    for (int jt = 0; jt < NTILE; jt++) {
        if (jt + 1 < NTILE) cp_wait1(); else cp_wait0();
        __syncthreads();
        if (jt + 2 < NTILE) loadKV((jt + 2) * 64, (jt + 2) % 3);
        const int st = jt % 3;

        // S = Q @ K^T  (16 rows x 64 cols per warp)
        float4 acc_s[8];
        #pragma unroll
        for (int i = 0; i < 8; i++) acc_s[i] = make_float4(0.f, 0.f, 0.f, 0.f);
        #pragma unroll
        for (int kd = 0; kd < 4; kd++) {
            #pragma unroll
            for (int inp = 0; inp < 8; inp += 2) {
                uint32_t b0, b1, b2, b3;
                ldsm_x4(b0, b1, b2, b3,
                        smem_u32(&Ks[st * 64 + inp * 8 + (sel >> 1) * 8 + idx][kd * 16 + (sel & 1) * 8]));
                mma_f16(acc_s[inp],     aq[kd][0], aq[kd][1], aq[kd][2], aq[kd][3], b0, b1);
                mma_f16(acc_s[inp + 1], aq[kd][0], aq[kd][1], aq[kd][2], aq[kd][3], b2, b3);
            }
        }

        // row max (fp32)
        float mx0 = -1e30f, mx1 = -1e30f;
        #pragma unroll
        for (int i = 0; i < 8; i++) {
            mx0 = fmaxf(mx0, fmaxf(acc_s[i].x, acc_s[i].y));
            mx1 = fmaxf(mx1, fmaxf(acc_s[i].z, acc_s[i].w));
        }
        mx0 = fmaxf(mx0, __shfl_xor_sync(0xffffffffu, mx0, 1));
        mx0 = fmaxf(mx0, __shfl_xor_sync(0xffffffffu, mx0, 2));
        mx1 = fmaxf(mx1, __shfl_xor_sync(0xffffffffu, mx1, 1));
        mx1 = fmaxf(mx1, __shfl_xor_sync(0xffffffffu, mx1, 2));
        float mn0 = fmaxf(mrow[0], mx0), mn1 = fmaxf(mrow[1], mx1);
        float al0 = exp2f((mrow[0] - mn0) * L2E), al1 = exp2f((mrow[1] - mn1) * L2E);
        mrow[0] = mn0; mrow[1] = mn1;
        const float nm0 = -mn0 * L2E, nm1 = -mn1 * L2E;

        // rescale O and l
        #pragma unroll
        for (int i = 0; i < 8; i++) {
            acc_o[i].x *= al0; acc_o[i].y *= al0;
            acc_o[i].z *= al1; acc_o[i].w *= al1;
        }
        acc_l.x *= al0; acc_l.y *= al0; acc_l.z *= al1; acc_l.w *= al1;

        // P in fp16 via ex2.approx.f16x2, then O += P @ V (V col 64 = ones -> l)
        #pragma unroll
        for (int ks = 0; ks < 4; ks++) {
            uint32_t a0 = ex2h2(pkh2(fmaf(acc_s[2 * ks].x, L2E, nm0),
                                     fmaf(acc_s[2 * ks].y, L2E, nm0)));
            uint32_t a1 = ex2h2(pkh2(fmaf(acc_s[2 * ks].z, L2E, nm1),
                                     fmaf(acc_s[2 * ks].w, L2E, nm1)));
            uint32_t a2 = ex2h2(pkh2(fmaf(acc_s[2 * ks + 1].x, L2E, nm0),
                                     fmaf(acc_s[2 * ks + 1].y, L2E, nm0)));
            uint32_t a3 = ex2h2(pkh2(fmaf(acc_s[2 * ks + 1].z, L2E, nm1),
                                     fmaf(acc_s[2 * ks + 1].w, L2E, nm1)));
            #pragma unroll
            for (int dp = 0; dp < 4; dp++) {
                uint32_t b0, b1, b2, b3;
                ldsm_x4_t(b0, b1, b2, b3,
                          smem_u32(&Vs[st * 64 + ks * 16 + (sel & 1) * 8 + idx][dp * 16 + (sel >> 1) * 8]));
                mma_f16(acc_o[2 * dp],     a0, a1, a2, a3, b0, b1);
                mma_f16(acc_o[2 * dp + 1], a0, a1, a2, a3, b2, b3);
            }
            {
                uint32_t b0, b1;
                ldsm_x2_t(b0, b1,
                          smem_u32(&Vs[st * 64 + ks * 16 + ((lane >> 3) & 1) * 8 + idx][64]));
                mma_f16(acc_l, a0, a1, a2, a3, b0, b1);
            }
        }
    }

    // l lives in acc_l.x (rows r0) / acc_l.z (rows r0+8) of quad-leader lanes
    float l0 = __shfl_sync(0xffffffffu, acc_l.x, lane & 0x1C);
    float l1 = __shfl_sync(0xffffffffu, acc_l.z, lane & 0x1C);
    float inv0 = 1.0f / l0, inv1 = 1.0f / l1;

    const int r0 = lane >> 2;
    #pragma unroll
    for (int df = 0; df < 8; df++) {
        int col = h * DD + df * 8 + (lane & 3) * 2;
        int n = n0 + wid * 16 + r0;
        *(__half2*)(y + (tok0 + n) * CC + col) =
            __floats2half2_rn(acc_o[df].x * inv0, acc_o[df].y * inv0);
        *(__half2*)(y + (tok0 + n + 8) * CC + col) =
            __floats2half2_rn(acc_o[df].z * inv1, acc_o[df].w * inv1);
    }
}

// ---------------- launch ----------------
extern "C" void kernel_launch(void* const* d_in, const int* in_sizes, int n_in,
                              void* d_out, int out_size)
{
    const float* x      = (const float*)d_in[0];
    const float* Wq     = (const float*)d_in[1];
    const float* Wk     = (const float*)d_in[2];
    const float* Wv     = (const float*)d_in[3];
    const float* Wp     = (const float*)d_in[4];
    const float* bp     = (const float*)d_in[5];
    const float* W1     = (const float*)d_in[6];
    const float* b1     = (const float*)d_in[7];
    const float* W2     = (const float*)d_in[8];
    const float* b2     = (const float*)d_in[9];
    const float* gamma1 = (const float*)d_in[10];
    const float* beta1  = (const float*)d_in[11];
    const float* gamma2 = (const float*)d_in[12];
    const float* beta2  = (const float*)d_in[13];
    float* out = (float*)d_out;

    __half *xn, *qkv, *y, *xn2, *hb, *wqkv, *wp, *w1, *w2;
    float *x1;
    cudaGetSymbolAddress((void**)&xn,   g_xn);
    cudaGetSymbolAddress((void**)&qkv,  g_qkv);
    cudaGetSymbolAddress((void**)&y,    g_y);
    cudaGetSymbolAddress((void**)&x1,   g_x1);
    cudaGetSymbolAddress((void**)&xn2,  g_xn2);
    cudaGetSymbolAddress((void**)&hb,   g_h);
    cudaGetSymbolAddress((void**)&wqkv, g_wqkv);
    cudaGetSymbolAddress((void**)&wp,   g_wp);
    cudaGetSymbolAddress((void**)&w1,   g_w1);
    cudaGetSymbolAddress((void**)&w2,   g_w2);

    cudaFuncSetAttribute(flash_kernel, cudaFuncAttributeMaxDynamicSharedMemorySize, FLASH_SMEM_B);
    cudaFuncSetAttribute(h_gemm_kernel, cudaFuncAttributeMaxDynamicSharedMemorySize, GEMM_SMEM);

    // 0) all weight conversions in ONE launch (qscale folded into Wq)
    conv_all_kernel<<<12288, 256>>>(Wq, Wk, Wv, Wp, W1, W2, wqkv, wp, w1, w2);

    // 1) LN1 -> fp16
    layernorm_kernel<<<TT, 256>>>(x, gamma1, beta1, xn);

    // 2) fused QKV projection: [T,C] @ [C,3C]
    {
        dim3 g(3 * CC / 128, TT / 256);
        h_gemm_kernel<<<g, 512, GEMM_SMEM>>>(xn, wqkv, nullptr, nullptr, nullptr, qkv,
                                             3 * CC, CC, 0);
    }

    // 3) fused flash attention
    {
        dim3 g(NN / 128, BB * HH);
        flash_kernel<<<g, 256, FLASH_SMEM_B>>>(qkv, y);
    }

    // 4) output projection + residual: x1 = x + y@Wp + bp (fp32 out)
    {
        dim3 g(CC / 128, TT / 256);
        h_gemm_kernel<<<g, 512, GEMM_SMEM>>>(y, wp, bp, x, x1, nullptr, CC, CC, 0);
    }

    // 5) LN2 -> fp16
    layernorm_kernel<<<TT, 256>>>(x1, gamma2, beta2, xn2);

    // 6) MLP
    {
        dim3 g(FF / 128, TT / 256);
        h_gemm_kernel<<<g, 512, GEMM_SMEM>>>(xn2, w1, b1, nullptr, nullptr, hb, FF, CC, 1);
    }
    {
        dim3 g(CC / 128, TT / 256);
        h_gemm_kernel<<<g, 512, GEMM_SMEM>>>(hb, w2, b2, x1, out, nullptr, CC, FF, 0);
    }
}

// round 12
// speedup vs baseline: 1.0861x; 1.0861x over previous
#include <cuda_runtime.h>
#include <cuda_fp16.h>
#include <math.h>
#include <stdint.h>

#define BB 2
#define NN 2048
#define CC 1024
#define HH 16
#define DD 64
#define FF 4096
#define TT (BB*NN)          // 4096 tokens

// ---------------- scratch (device globals) ----------------
__device__ __half g_xn  [(size_t)TT*CC];
__device__ __half g_qkv [(size_t)TT*3*CC];
__device__ __half g_y   [(size_t)TT*CC];
__device__ float  g_x1  [(size_t)TT*CC];
__device__ __half g_xn2 [(size_t)TT*CC];
__device__ __half g_h   [(size_t)TT*FF];
__device__ __half g_wqkv[(size_t)CC*3*CC];
__device__ __half g_wp  [(size_t)CC*CC];
__device__ __half g_w1  [(size_t)CC*FF];
__device__ __half g_w2  [(size_t)FF*CC];

// ---------------- helpers ----------------
__device__ __forceinline__ uint32_t smem_u32(const void* p) {
    return (uint32_t)__cvta_generic_to_shared(p);
}

__device__ __forceinline__ void mma_f16(float4& d,
    uint32_t a0, uint32_t a1, uint32_t a2, uint32_t a3, uint32_t b0, uint32_t b1)
{
    asm volatile(
        "mma.sync.aligned.m16n8k16.row.col.f32.f16.f16.f32 "
        "{%0,%1,%2,%3}, {%4,%5,%6,%7}, {%8,%9}, {%0,%1,%2,%3};\n"
        : "+f"(d.x), "+f"(d.y), "+f"(d.z), "+f"(d.w)
        : "r"(a0), "r"(a1), "r"(a2), "r"(a3), "r"(b0), "r"(b1));
}

__device__ __forceinline__ void ldsm_x4(uint32_t& r0, uint32_t& r1, uint32_t& r2, uint32_t& r3,
                                        uint32_t addr) {
    asm volatile("ldmatrix.sync.aligned.m8n8.x4.shared.b16 {%0,%1,%2,%3}, [%4];"
        : "=r"(r0), "=r"(r1), "=r"(r2), "=r"(r3) : "r"(addr));
}
__device__ __forceinline__ void ldsm_x4_t(uint32_t& r0, uint32_t& r1, uint32_t& r2, uint32_t& r3,
                                          uint32_t addr) {
    asm volatile("ldmatrix.sync.aligned.m8n8.x4.trans.shared.b16 {%0,%1,%2,%3}, [%4];"
        : "=r"(r0), "=r"(r1), "=r"(r2), "=r"(r3) : "r"(addr));
}
__device__ __forceinline__ void ldsm_x2_t(uint32_t& r0, uint32_t& r1, uint32_t addr) {
    asm volatile("ldmatrix.sync.aligned.m8n8.x2.trans.shared.b16 {%0,%1}, [%2];"
        : "=r"(r0), "=r"(r1) : "r"(addr));
}

__device__ __forceinline__ void cp16(void* smem_dst, const void* gsrc) {
    uint32_t d = smem_u32(smem_dst);
    asm volatile("cp.async.cg.shared.global [%0], [%1], 16;\n" :: "r"(d), "l"(gsrc));
}
__device__ __forceinline__ void cp_commit() { asm volatile("cp.async.commit_group;\n"); }
__device__ __forceinline__ void cp_wait0() { asm volatile("cp.async.wait_group 0;\n"); }
__device__ __forceinline__ void cp_wait1() { asm volatile("cp.async.wait_group 1;\n"); }
__device__ __forceinline__ void cp_wait2() { asm volatile("cp.async.wait_group 2;\n"); }

__device__ __forceinline__ uint32_t pkh2(float x, float y) {
    __half2 h = __floats2half2_rn(x, y);
    return *(uint32_t*)&h;
}
__device__ __forceinline__ uint32_t ex2h2(uint32_t a) {
    uint32_t d;
    asm("ex2.approx.f16x2 %0, %1;" : "=r"(d) : "r"(a));
    return d;
}

#define L2E 1.4426950408889634f

__device__ __forceinline__ float blockReduceSum256(float v) {
    __shared__ float sm[8];
    #pragma unroll
    for (int o = 16; o > 0; o >>= 1) v += __shfl_xor_sync(0xffffffffu, v, o);
    __syncthreads();
    if ((threadIdx.x & 31) == 0) sm[threadIdx.x >> 5] = v;
    __syncthreads();
    float t = 0.f;
    #pragma unroll
    for (int i = 0; i < 8; i++) t += sm[i];
    return t;
}

// ---------------- fused weight conversion: all 6 weights in one launch --------------
__global__ __launch_bounds__(256) void conv_all_kernel(
    const float* __restrict__ Wq, const float* __restrict__ Wk,
    const float* __restrict__ Wv, const float* __restrict__ Wp,
    const float* __restrict__ W1, const float* __restrict__ W2,
    __half* __restrict__ wqkv, __half* __restrict__ wp,
    __half* __restrict__ w1, __half* __restrict__ w2)
{
    const int blk = blockIdx.x;
    const float* in;
    __half* out;
    int cols, ldo, colofs, i0;
    float scale = 1.0f;
    if (blk < 4096) {
        cols = CC;
        if (blk < 1024)      { in = Wq; out = wqkv; ldo = 3 * CC; colofs = 0;      i0 = 0;    scale = 0.125f; }
        else if (blk < 2048) { in = Wk; out = wqkv; ldo = 3 * CC; colofs = CC;     i0 = 1024; }
        else if (blk < 3072) { in = Wv; out = wqkv; ldo = 3 * CC; colofs = 2 * CC; i0 = 2048; }
        else                 { in = Wp; out = wp;   ldo = CC;     colofs = 0;      i0 = 3072; }
    } else if (blk < 8192)   { in = W1; out = w1; cols = FF; ldo = FF; colofs = 0; i0 = 4096; }
    else                     { in = W2; out = w2; cols = CC; ldo = CC; colofs = 0; i0 = 8192; }

    int i = (blk - i0) * 256 + threadIdx.x;
    float4 v = ((const float4*)in)[i];
    int c4 = cols >> 2;
    int row = i / c4;
    int col = (i - row * c4) * 4;
    __half2* o = (__half2*)(out + (size_t)row * ldo + colofs + col);
    o[0] = __floats2half2_rn(v.x * scale, v.y * scale);
    o[1] = __floats2half2_rn(v.z * scale, v.w * scale);
}

// ---------------- layernorm: fp32 in -> fp16 out ----------------
__global__ __launch_bounds__(256) void layernorm_kernel(
    const float* __restrict__ x, const float* __restrict__ gamma,
    const float* __restrict__ beta, __half* __restrict__ out)
{
    const size_t row = (size_t)blockIdx.x * CC;
    const int c = threadIdx.x * 4;
    float4 v = *(const float4*)(x + row + c);

    float s = v.x + v.y + v.z + v.w;
    s = blockReduceSum256(s);
    float mu = s * (1.0f / CC);

    float dx = v.x - mu, dy = v.y - mu, dz = v.z - mu, dw = v.w - mu;
    float ss = dx*dx + dy*dy + dz*dz + dw*dw;
    ss = blockReduceSum256(ss);
    float rstd = rsqrtf(ss * (1.0f / CC) + 1e-6f);

    float4 g = *(const float4*)(gamma + c);
    float4 b = *(const float4*)(beta + c);
    __half2* o = (__half2*)(out + row + c);
    o[0] = __floats2half2_rn(dx * rstd * g.x + b.x, dy * rstd * g.y + b.y);
    o[1] = __floats2half2_rn(dz * rstd * g.z + b.z, dw * rstd * g.w + b.w);
}

// ---------------- fp16 GEMM 128x128x64, 256 thr, 3-stage ring, 2 CTA/SM ----------
// A [M][K] fp16 row-major, B [K][N] fp16 row-major
// smem: As [3*128][72], Bs [3*64][136]  -> 107520 B dynamic (2 CTAs = 215 KB)
#define GEMM_SMEM (3*128*72*2 + 3*64*136*2)

__global__ __launch_bounds__(256, 2) void h_gemm_kernel(
    const __half* __restrict__ A, const __half* __restrict__ Bm,
    const float* __restrict__ bias, const float* __restrict__ res,
    float* __restrict__ Cf, __half* __restrict__ Ch,
    int N, int K, int do_gelu)
{
    extern __shared__ char gsm[];
    __half (*As)[72]  = (__half(*)[72])gsm;                       // [3*128][72]
    __half (*Bs)[136] = (__half(*)[136])(gsm + 3 * 128 * 72 * 2); // [3*64][136]

    const int tid = threadIdx.x;
    const int lane = tid & 31;
    const int wid = tid >> 5;
    const int bx = blockIdx.x, by = blockIdx.y;
    const int m0w = (wid >> 2) * 64;
    const int n0w = (wid & 3) * 32;
    const int idx = lane & 7;
    const int sel = (lane >> 3) & 3;

    float4 acc[4][4];
    #pragma unroll
    for (int i = 0; i < 4; i++)
        #pragma unroll
        for (int j = 0; j < 4; j++) acc[i][j] = make_float4(0.f, 0.f, 0.f, 0.f);

    auto loadChunk = [&](int k0, int st) {
        #pragma unroll
        for (int i = 0; i < 4; i++) {
            int c = tid + i * 256;          // 1024 chunks for A (128x64)
            int r = c >> 3, c8 = (c & 7) * 8;
            cp16(&As[st * 128 + r][c8], A + (size_t)(by * 128 + r) * K + k0 + c8);
        }
        #pragma unroll
        for (int i = 0; i < 4; i++) {
            int c = tid + i * 256;          // 1024 chunks for B (64x128)
            int r = c >> 4, c8 = (c & 15) * 8;
            cp16(&Bs[st * 64 + r][c8], Bm + (size_t)(k0 + r) * N + bx * 128 + c8);
        }
        cp_commit();
    };

    const int KT = K >> 6;                  // 16 or 64
    loadChunk(0, 0);
    loadChunk(64, 1);
    for (int kt = 0; kt < KT; kt++) {
        if (kt + 1 < KT) cp_wait1(); else cp_wait0();
        __syncthreads();
        if (kt + 2 < KT) loadChunk((kt + 2) << 6, (kt + 2) % 3);

        const int st = kt % 3;
        #pragma unroll
        for (int kk = 0; kk < 64; kk += 16) {
            uint32_t af[4][4];
            #pragma unroll
            for (int im = 0; im < 4; im++)
                ldsm_x4(af[im][0], af[im][1], af[im][2], af[im][3],
                        smem_u32(&As[st * 128 + m0w + im * 16 + (lane & 15)][kk + ((lane >> 4) << 3)]));
            uint32_t bf[4][2];
            #pragma unroll
            for (int inp = 0; inp < 4; inp += 2)
                ldsm_x4_t(bf[inp][0], bf[inp][1], bf[inp + 1][0], bf[inp + 1][1],
                          smem_u32(&Bs[st * 64 + kk + (sel & 1) * 8 + idx][n0w + inp * 8 + (sel >> 1) * 8]));
            #pragma unroll
            for (int im = 0; im < 4; im++)
                #pragma unroll
                for (int in = 0; in < 4; in++)
                    mma_f16(acc[im][in], af[im][0], af[im][1], af[im][2], af[im][3],
                            bf[in][0], bf[in][1]);
        }
    }

    // epilogue
    #pragma unroll
    for (int im = 0; im < 4; im++) {
        #pragma unroll
        for (int in = 0; in < 4; in++) {
            int row = by * 128 + m0w + im * 16 + (lane >> 2);
            int col = bx * 128 + n0w + in * 8 + (lane & 3) * 2;
            #pragma unroll
            for (int half = 0; half < 2; half++) {
                int r = row + half * 8;
                float v0 = half ? acc[im][in].z : acc[im][in].x;
                float v1 = half ? acc[im][in].w : acc[im][in].y;
                if (bias) { v0 += bias[col]; v1 += bias[col + 1]; }
                if (do_gelu) {
                    v0 = 0.5f * v0 * (1.0f + erff(v0 * 0.70710678118654752f));
                    v1 = 0.5f * v1 * (1.0f + erff(v1 * 0.70710678118654752f));
                }
                if (res) {
                    v0 += res[(size_t)r * N + col];
                    v1 += res[(size_t)r * N + col + 1];
                }
                if (Ch) {
                    *(__half2*)(Ch + (size_t)r * N + col) = __floats2half2_rn(v0, v1);
                } else {
                    *(float2*)(Cf + (size_t)r * N + col) = make_float2(v0, v1);
                }
            }
        }
    }
}

// ---------------- fused flash attention: 64-key KV tiles, 3-stage ring, 2 CTA/SM ----
// grid (NN/128, B*H), 256 thr. Q tile 128 rows; KV tiles 64 rows, 3 stages.
// V smem col 64 = 1.0 (ones column) -> row sum l accumulates in extra MMA accum.
// smem: Q 128x72 + 3x64x72 (K) + 3x64x72 (V) = 73728 B
#define FLASH_SMEM_B ((128*72 + 3*64*72 + 3*64*72) * 2)

__global__ __launch_bounds__(256, 2) void flash_kernel(
    const __half* __restrict__ qkv, __half* __restrict__ y)
{
    extern __shared__ __half fsm[];
    __half (*Qs)[72] = (__half(*)[72])fsm;                            // 128x72
    __half (*Ks)[72] = (__half(*)[72])(fsm + 128 * 72);               // 3 x 64x72
    __half (*Vs)[72] = (__half(*)[72])(fsm + 128 * 72 + 3 * 64 * 72); // 3 x 64x72

    const int bh = blockIdx.y;
    const int b = bh >> 4, h = bh & 15;
    const int n0 = blockIdx.x * 128;
    const int tid = threadIdx.x;
    const int lane = tid & 31;
    const int wid = tid >> 5;
    const int idx = lane & 7;
    const int sel = (lane >> 3) & 3;

    const size_t tok0 = (size_t)b * NN;
    const __half* qb = qkv + h * DD;
    const __half* kb = qkv + CC + h * DD;
    const __half* vb = qkv + 2 * CC + h * DD;

    // Q tile: group 0
    #pragma unroll
    for (int i = 0; i < 4; i++) {
        int c = tid + i * 256;
        int r = c >> 3, c8 = (c & 7) * 8;
        cp16(&Qs[r][c8], qb + (tok0 + n0 + r) * (3 * CC) + c8);
    }
    cp_commit();

    auto loadKV = [&](int m0, int st) {
        #pragma unroll
        for (int i = 0; i < 2; i++) {
            int c = tid + i * 256;          // 512 chunks, 64 rows
            int r = c >> 3, c8 = (c & 7) * 8;
            cp16(&Ks[st * 64 + r][c8], kb + (tok0 + m0 + r) * (3 * CC) + c8);
        }
        #pragma unroll
        for (int i = 0; i < 2; i++) {
            int c = tid + i * 256;
            int r = c >> 3, c8 = (c & 7) * 8;
            cp16(&Vs[st * 64 + r][c8], vb + (tok0 + m0 + r) * (3 * CC) + c8);
        }
        cp_commit();
    };

    loadKV(0, 0);    // group 1
    loadKV(64, 1);   // group 2

    // ones column at V col 64, zeros 65-71 (all 3 stages = 192 rows; cols never overwritten)
    if (tid < 192) {
        __half* p = &Vs[tid][64];
        p[0] = __float2half(1.0f);
        #pragma unroll
        for (int j = 1; j < 8; j++) p[j] = __float2half(0.0f);
    }

    // Q ready after wait<=2 (groups 1,2 may still be in flight)
    cp_wait2();
    __syncthreads();
    uint32_t aq[4][4];
    #pragma unroll
    for (int kd = 0; kd < 4; kd++)
        ldsm_x4(aq[kd][0], aq[kd][1], aq[kd][2], aq[kd][3],
                smem_u32(&Qs[wid * 16 + (lane & 15)][kd * 16 + ((lane >> 4) << 3)]));

    float4 acc_o[8];
    float4 acc_l = make_float4(0.f, 0.f, 0.f, 0.f);
    #pragma unroll
    for (int i = 0; i < 8; i++) acc_o[i] = make_float4(0.f, 0.f, 0.f, 0.f);
    float mrow[2] = {-1e30f, -1e30f};

    const int NTILE = NN / 64;        // 32 KV tiles of 64 keys
    for (int jt = 0; jt < NTILE; jt++) {
        if (jt + 1 < NTILE) cp_wait1(); else cp_wait0();
        __syncthreads();
        if (jt + 2 < NTILE) loadKV((jt + 2) * 64, (jt + 2) % 3);
        const int st = jt % 3;

        // S = Q @ K^T  (16 rows x 64 cols per warp)
        float4 acc_s[8];
        #pragma unroll
        for (int i = 0; i < 8; i++) acc_s[i] = make_float4(0.f, 0.f, 0.f, 0.f);
        #pragma unroll
        for (int kd = 0; kd < 4; kd++) {
            #pragma unroll
            for (int inp = 0; inp < 8; inp += 2) {
                uint32_t b0, b1, b2, b3;
                ldsm_x4(b0, b1, b2, b3,
                        smem_u32(&Ks[st * 64 + inp * 8 + (sel >> 1) * 8 + idx][kd * 16 + (sel & 1) * 8]));
                mma_f16(acc_s[inp],     aq[kd][0], aq[kd][1], aq[kd][2], aq[kd][3], b0, b1);
                mma_f16(acc_s[inp + 1], aq[kd][0], aq[kd][1], aq[kd][2], aq[kd][3], b2, b3);
            }
        }

        // row max (fp32)
        float mx0 = -1e30f, mx1 = -1e30f;
        #pragma unroll
        for (int i = 0; i < 8; i++) {
            mx0 = fmaxf(mx0, fmaxf(acc_s[i].x, acc_s[i].y));
            mx1 = fmaxf(mx1, fmaxf(acc_s[i].z, acc_s[i].w));
        }
        mx0 = fmaxf(mx0, __shfl_xor_sync(0xffffffffu, mx0, 1));
        mx0 = fmaxf(mx0, __shfl_xor_sync(0xffffffffu, mx0, 2));
        mx1 = fmaxf(mx1, __shfl_xor_sync(0xffffffffu, mx1, 1));
        mx1 = fmaxf(mx1, __shfl_xor_sync(0xffffffffu, mx1, 2));
        float mn0 = fmaxf(mrow[0], mx0), mn1 = fmaxf(mrow[1], mx1);
        float al0 = exp2f((mrow[0] - mn0) * L2E), al1 = exp2f((mrow[1] - mn1) * L2E);
        mrow[0] = mn0; mrow[1] = mn1;
        const float nm0 = -mn0 * L2E, nm1 = -mn1 * L2E;

        // rescale O and l
        #pragma unroll
        for (int i = 0; i < 8; i++) {
            acc_o[i].x *= al0; acc_o[i].y *= al0;
            acc_o[i].z *= al1; acc_o[i].w *= al1;
        }
        acc_l.x *= al0; acc_l.y *= al0; acc_l.z *= al1; acc_l.w *= al1;

        // P in fp16 via ex2.approx.f16x2, then O += P @ V (V col 64 = ones -> l)
        #pragma unroll
        for (int ks = 0; ks < 4; ks++) {
            uint32_t a0 = ex2h2(pkh2(fmaf(acc_s[2 * ks].x, L2E, nm0),
                                     fmaf(acc_s[2 * ks].y, L2E, nm0)));
            uint32_t a1 = ex2h2(pkh2(fmaf(acc_s[2 * ks].z, L2E, nm1),
                                     fmaf(acc_s[2 * ks].w, L2E, nm1)));
            uint32_t a2 = ex2h2(pkh2(fmaf(acc_s[2 * ks + 1].x, L2E, nm0),
                                     fmaf(acc_s[2 * ks + 1].y, L2E, nm0)));
            uint32_t a3 = ex2h2(pkh2(fmaf(acc_s[2 * ks + 1].z, L2E, nm1),
                                     fmaf(acc_s[2 * ks + 1].w, L2E, nm1)));
            #pragma unroll
            for (int dp = 0; dp < 4; dp++) {
                uint32_t b0, b1, b2, b3;
                ldsm_x4_t(b0, b1, b2, b3,
                          smem_u32(&Vs[st * 64 + ks * 16 + (sel & 1) * 8 + idx][dp * 16 + (sel >> 1) * 8]));
                mma_f16(acc_o[2 * dp],     a0, a1, a2, a3, b0, b1);
                mma_f16(acc_o[2 * dp + 1], a0, a1, a2, a3, b2, b3);
            }
            {
                uint32_t b0, b1;
                ldsm_x2_t(b0, b1,
                          smem_u32(&Vs[st * 64 + ks * 16 + ((lane >> 3) & 1) * 8 + idx][64]));
                mma_f16(acc_l, a0, a1, a2, a3, b0, b1);
            }
        }
    }

    // l lives in acc_l.x (rows r0) / acc_l.z (rows r0+8) of quad-leader lanes
    float l0 = __shfl_sync(0xffffffffu, acc_l.x, lane & 0x1C);
    float l1 = __shfl_sync(0xffffffffu, acc_l.z, lane & 0x1C);
    float inv0 = 1.0f / l0, inv1 = 1.0f / l1;

    const int r0 = lane >> 2;
    #pragma unroll
    for (int df = 0; df < 8; df++) {
        int col = h * DD + df * 8 + (lane & 3) * 2;
        int n = n0 + wid * 16 + r0;
        *(__half2*)(y + (tok0 + n) * CC + col) =
            __floats2half2_rn(acc_o[df].x * inv0, acc_o[df].y * inv0);
        *(__half2*)(y + (tok0 + n + 8) * CC + col) =
            __floats2half2_rn(acc_o[df].z * inv1, acc_o[df].w * inv1);
    }
}

// ---------------- launch ----------------
extern "C" void kernel_launch(void* const* d_in, const int* in_sizes, int n_in,
                              void* d_out, int out_size)
{
    const float* x      = (const float*)d_in[0];
    const float* Wq     = (const float*)d_in[1];
    const float* Wk     = (const float*)d_in[2];
    const float* Wv     = (const float*)d_in[3];
    const float* Wp     = (const float*)d_in[4];
    const float* bp     = (const float*)d_in[5];
    const float* W1     = (const float*)d_in[6];
    const float* b1     = (const float*)d_in[7];
    const float* W2     = (const float*)d_in[8];
    const float* b2     = (const float*)d_in[9];
    const float* gamma1 = (const float*)d_in[10];
    const float* beta1  = (const float*)d_in[11];
    const float* gamma2 = (const float*)d_in[12];
    const float* beta2  = (const float*)d_in[13];
    float* out = (float*)d_out;

    __half *xn, *qkv, *y, *xn2, *hb, *wqkv, *wp, *w1, *w2;
    float *x1;
    cudaGetSymbolAddress((void**)&xn,   g_xn);
    cudaGetSymbolAddress((void**)&qkv,  g_qkv);
    cudaGetSymbolAddress((void**)&y,    g_y);
    cudaGetSymbolAddress((void**)&x1,   g_x1);
    cudaGetSymbolAddress((void**)&xn2,  g_xn2);
    cudaGetSymbolAddress((void**)&hb,   g_h);
    cudaGetSymbolAddress((void**)&wqkv, g_wqkv);
    cudaGetSymbolAddress((void**)&wp,   g_wp);
    cudaGetSymbolAddress((void**)&w1,   g_w1);
    cudaGetSymbolAddress((void**)&w2,   g_w2);

    cudaFuncSetAttribute(flash_kernel, cudaFuncAttributeMaxDynamicSharedMemorySize, FLASH_SMEM_B);
    cudaFuncSetAttribute(h_gemm_kernel, cudaFuncAttributeMaxDynamicSharedMemorySize, GEMM_SMEM);

    // 0) all weight conversions in ONE launch (qscale folded into Wq)
    conv_all_kernel<<<12288, 256>>>(Wq, Wk, Wv, Wp, W1, W2, wqkv, wp, w1, w2);

    // 1) LN1 -> fp16
    layernorm_kernel<<<TT, 256>>>(x, gamma1, beta1, xn);

    // 2) fused QKV projection: [T,C] @ [C,3C]
    {
        dim3 g(3 * CC / 128, TT / 128);
        h_gemm_kernel<<<g, 256, GEMM_SMEM>>>(xn, wqkv, nullptr, nullptr, nullptr, qkv,
                                             3 * CC, CC, 0);
    }

    // 3) fused flash attention
    {
        dim3 g(NN / 128, BB * HH);
        flash_kernel<<<g, 256, FLASH_SMEM_B>>>(qkv, y);
    }

    // 4) output projection + residual: x1 = x + y@Wp + bp (fp32 out)
    {
        dim3 g(CC / 128, TT / 128);
        h_gemm_kernel<<<g, 256, GEMM_SMEM>>>(y, wp, bp, x, x1, nullptr, CC, CC, 0);
    }

    // 5) LN2 -> fp16
    layernorm_kernel<<<TT, 256>>>(x1, gamma2, beta2, xn2);

    // 6) MLP
    {
        dim3 g(FF / 128, TT / 128);
        h_gemm_kernel<<<g, 256, GEMM_SMEM>>>(xn2, w1, b1, nullptr, nullptr, hb, FF, CC, 1);
    }
    {
        dim3 g(CC / 128, TT / 128);
        h_gemm_kernel<<<g, 256, GEMM_SMEM>>>(hb, w2, b2, x1, out, nullptr, CC, FF, 0);
    }
}